// round 4
// baseline (speedup 1.0000x reference)
#include <cuda_runtime.h>
#include <cstdint>

// ----------------------------------------------------------------------------
// MultiHeadAttn: x[2,4096,512], Wq/Wv[8,512,64], Wup[512,512]
// Pipeline:
//   1) repack Wq,Wv -> Wpk[512,1024] (col c<512 = Q head cols, c>=512 = V)
//   2) sgemm: QV[8192,1024] = x[8192,512] @ Wpk           (f32x2 FFMA2)
//   3) band attention (|i-j|<=10, i!=j) -> Cbuf[8192,512] (head-concat layout)
//   4) sgemm: out[8192,512] = Cbuf @ Wup
// ----------------------------------------------------------------------------

#define M_ROWS   8192
#define N_SEQ    4096
#define DMODEL   512
#define NHEAD    8
#define DHEAD    64
#define CONTEXT  10

// scratch (allocation-free rule: __device__ globals)
__device__ float g_QV[M_ROWS * 1024];   // Q cols 0..511, V cols 512..1023
__device__ float g_C [M_ROWS * 512];
__device__ float g_W [512 * 1024];

// ---------------- f32x2 helpers ----------------
typedef unsigned long long u64;

__device__ __forceinline__ u64 pack2(float lo, float hi) {
    u64 r;
    asm("mov.b64 %0, {%1, %2};" : "=l"(r) : "f"(lo), "f"(hi));
    return r;
}
__device__ __forceinline__ void unpack2(u64 v, float &lo, float &hi) {
    asm("mov.b64 {%0, %1}, %2;" : "=f"(lo), "=f"(hi) : "l"(v));
}
__device__ __forceinline__ void ffma2(u64 &d, u64 a, u64 b) {
    // d = a * b + d   (packed 2x fp32)
    asm("fma.rn.f32x2 %0, %1, %2, %0;" : "+l"(d) : "l"(a), "l"(b));
}

// ---------------- weight repack ----------------
// Wpk[d*1024 + c]: c<512 -> Wq[h=c/64, d, k=c%64], else Wv
__global__ void repack_kernel(const float* __restrict__ Wq,
                              const float* __restrict__ Wv,
                              float* __restrict__ W) {
    int idx = blockIdx.x * 256 + threadIdx.x;     // [0, 512*1024)
    if (idx >= 512 * 1024) return;
    int d = idx >> 10;
    int c = idx & 1023;
    float v;
    if (c < 512) {
        int h = c >> 6, k = c & 63;
        v = Wq[h * (512 * 64) + d * 64 + k];
    } else {
        int cc = c - 512;
        int h = cc >> 6, k = cc & 63;
        v = Wv[h * (512 * 64) + d * 64 + k];
    }
    W[idx] = v;
}

// ---------------- fp32 SGEMM, 128x128x16 tile, f32x2 inner ----------------
// C[M,N] = A[M,K] @ B[K,N], all row-major. M%128==0, N%128==0, K%16==0.
__global__ __launch_bounds__(256, 2)
void sgemm_f32x2(const float* __restrict__ A, const float* __restrict__ B,
                 float* __restrict__ C, int M, int N, int K) {
    __shared__ float As[16][128];
    __shared__ float Bs[16][128];

    const int tid = threadIdx.x;
    const int tm  = tid >> 4;        // 0..15
    const int tn  = tid & 15;        // 0..15
    const int bm  = blockIdx.y * 128;
    const int bn  = blockIdx.x * 128;

    u64 acc[8][4];
    #pragma unroll
    for (int i = 0; i < 8; i++)
        #pragma unroll
        for (int j = 0; j < 4; j++)
            acc[i][j] = 0ull;        // bits of (0.f, 0.f)

    for (int k0 = 0; k0 < K; k0 += 16) {
        // ---- load A tile (transpose to As[k][m]) ----
        #pragma unroll
        for (int f = 0; f < 2; f++) {
            int idx = tid + f * 256;         // 0..511 float4s
            int m   = idx >> 2;              // 0..127
            int kq  = idx & 3;               // 0..3
            float4 v = *(const float4*)(A + (bm + m) * K + k0 + kq * 4);
            As[kq * 4 + 0][m] = v.x;
            As[kq * 4 + 1][m] = v.y;
            As[kq * 4 + 2][m] = v.z;
            As[kq * 4 + 3][m] = v.w;
        }
        // ---- load B tile ----
        #pragma unroll
        for (int f = 0; f < 2; f++) {
            int idx = tid + f * 256;         // 0..511 float4s
            int kk  = idx >> 5;              // 0..15
            int nq  = idx & 31;              // 0..31
            *(float4*)&Bs[kk][nq * 4] =
                *(const float4*)(B + (k0 + kk) * N + bn + nq * 4);
        }
        __syncthreads();

        #pragma unroll
        for (int k = 0; k < 16; k++) {
            float4 a0 = *(const float4*)&As[k][tm * 8];
            float4 a1 = *(const float4*)&As[k][tm * 8 + 4];
            float4 b0 = *(const float4*)&Bs[k][tn * 8];
            float4 b1 = *(const float4*)&Bs[k][tn * 8 + 4];
            u64 bp[4];
            bp[0] = pack2(b0.x, b0.y);
            bp[1] = pack2(b0.z, b0.w);
            bp[2] = pack2(b1.x, b1.y);
            bp[3] = pack2(b1.z, b1.w);
            float am[8] = {a0.x, a0.y, a0.z, a0.w, a1.x, a1.y, a1.z, a1.w};
            #pragma unroll
            for (int i = 0; i < 8; i++) {
                u64 ad = pack2(am[i], am[i]);
                ffma2(acc[i][0], ad, bp[0]);
                ffma2(acc[i][1], ad, bp[1]);
                ffma2(acc[i][2], ad, bp[2]);
                ffma2(acc[i][3], ad, bp[3]);
            }
        }
        __syncthreads();
    }

    // ---- epilogue ----
    #pragma unroll
    for (int i = 0; i < 8; i++) {
        int row = bm + tm * 8 + i;
        float o[8];
        unpack2(acc[i][0], o[0], o[1]);
        unpack2(acc[i][1], o[2], o[3]);
        unpack2(acc[i][2], o[4], o[5]);
        unpack2(acc[i][3], o[6], o[7]);
        float4 w0 = make_float4(o[0], o[1], o[2], o[3]);
        float4 w1 = make_float4(o[4], o[5], o[6], o[7]);
        *(float4*)(C + row * N + bn + tn * 8)     = w0;
        *(float4*)(C + row * N + bn + tn * 8 + 4) = w1;
    }
}

// ---------------- band attention ----------------
// One block = (b, h, 64-row i-tile). 256 threads = 8 warps, 8 rows/warp.
// Vs holds rows [i0-10, i0+73] (84 rows), pitch 65 -> conflict-free
// lane-per-j score phase AND lane-per-k accumulate phase.
#define TILE_I 64
#define VROWS  (TILE_I + 2 * CONTEXT)   // 84
#define PITCH  65

__global__ __launch_bounds__(256)
void band_attn_kernel(const float* __restrict__ QV, float* __restrict__ Cb) {
    __shared__ float Vs[VROWS * PITCH];   // 84*65 floats
    __shared__ float Qs[TILE_I * PITCH];  // 64*65 floats

    const int bx   = blockIdx.x;          // [0, 1024)
    const int tile = bx & 63;
    const int h    = (bx >> 6) & 7;
    const int b    = bx >> 9;
    const int i0   = tile * TILE_I;
    const int tid  = threadIdx.x;
    const int lane = tid & 31;
    const int warp = tid >> 5;

    // load V band rows (zero-fill out-of-range rows: avoids NaN poison)
    for (int idx = tid; idx < VROWS * 16; idx += 256) {
        int r  = idx >> 4;
        int kq = idx & 15;
        int j  = i0 - CONTEXT + r;
        float4 v = make_float4(0.f, 0.f, 0.f, 0.f);
        if (j >= 0 && j < N_SEQ)
            v = *(const float4*)(QV + (b * N_SEQ + j) * 1024 + 512 + h * 64 + kq * 4);
        float* p = &Vs[r * PITCH + kq * 4];
        p[0] = v.x; p[1] = v.y; p[2] = v.z; p[3] = v.w;
    }
    // load Q rows
    for (int idx = tid; idx < TILE_I * 16; idx += 256) {
        int r  = idx >> 4;
        int kq = idx & 15;
        float4 v = *(const float4*)(QV + (b * N_SEQ + i0 + r) * 1024 + h * 64 + kq * 4);
        float* p = &Qs[r * PITCH + kq * 4];
        p[0] = v.x; p[1] = v.y; p[2] = v.z; p[3] = v.w;
    }
    __syncthreads();

    for (int t = 0; t < 8; t++) {
        int il = warp * 8 + t;          // local row
        int i  = i0 + il;               // global row within sequence

        // ---- phase A: lane L -> offset d = L-10, score = Q_i . V_{i+d} / 16
        float s = -1e30f;
        if (lane < 21 && lane != CONTEXT) {
            int j = i + lane - CONTEXT;
            if (j >= 0 && j < N_SEQ) {
                const float* qp = &Qs[il * PITCH];
                const float* vp = &Vs[(il + lane) * PITCH];  // rows conflict-free (pitch 65)
                float acc = 0.f;
                #pragma unroll
                for (int k = 0; k < 64; k++)
                    acc += qp[k] * vp[k];
                s = acc * (1.0f / 16.0f);
            }
        }

        // ---- phase B: softmax across band lanes
        float mx = s;
        #pragma unroll
        for (int o = 16; o > 0; o >>= 1)
            mx = fmaxf(mx, __shfl_xor_sync(0xffffffffu, mx, o));
        float p = __expf(s - mx);       // masked lanes: exp(-1e30) = 0
        float sum = p;
        #pragma unroll
        for (int o = 16; o > 0; o >>= 1)
            sum += __shfl_xor_sync(0xffffffffu, sum, o);
        float w = p / sum;

        // ---- phase C: C_i[k] = sum_j w_j * V_j[k]; lane handles k=lane, lane+32
        float a0 = 0.f, a1 = 0.f;
        #pragma unroll
        for (int jj = 0; jj < 21; jj++) {
            float wj = __shfl_sync(0xffffffffu, w, jj);
            const float* vp = &Vs[(il + jj) * PITCH];
            a0 += wj * vp[lane];
            a1 += wj * vp[lane + 32];
        }
        float* cp = Cb + (b * N_SEQ + i) * 512 + h * 64;
        cp[lane]      = a0;
        cp[lane + 32] = a1;
    }
}

// ---------------- launch ----------------
extern "C" void kernel_launch(void* const* d_in, const int* in_sizes, int n_in,
                              void* d_out, int out_size) {
    const float* x   = (const float*)d_in[0];
    const float* Wq  = (const float*)d_in[1];
    const float* Wv  = (const float*)d_in[2];
    const float* Wup = (const float*)d_in[3];
    float* out = (float*)d_out;

    float *qv, *cbuf, *wpk;
    cudaGetSymbolAddress((void**)&qv,   g_QV);
    cudaGetSymbolAddress((void**)&cbuf, g_C);
    cudaGetSymbolAddress((void**)&wpk,  g_W);

    // 1) repack weights -> [512, 1024]
    repack_kernel<<<(512 * 1024) / 256, 256>>>(Wq, Wv, wpk);
    // 2) QV = x @ Wpk : [8192,512] x [512,1024]
    sgemm_f32x2<<<dim3(1024 / 128, M_ROWS / 128), 256>>>(x, wpk, qv,
                                                         M_ROWS, 1024, 512);
    // 3) band attention -> Cbuf [8192,512]
    band_attn_kernel<<<2 * NHEAD * (N_SEQ / TILE_I), 256>>>(qv, cbuf);
    // 4) out = Cbuf @ Wup : [8192,512] x [512,512]
    sgemm_f32x2<<<dim3(512 / 128, M_ROWS / 128), 256>>>(cbuf, Wup, out,
                                                        M_ROWS, 512, 512);
}

// round 6
// speedup vs baseline: 1.8144x; 1.8144x over previous
#include <cuda_runtime.h>
#include <cuda_bf16.h>
#include <cstdint>

// ----------------------------------------------------------------------------
// MultiHeadAttn via bf16 split + mma.sync (HMMA, family-target safe):
//   fp32 -> (hi, lo) bf16 split; GEMMs run as bf16 K'=1536 = [hi|lo|hi]x[hi|hi|lo]
//   1) convert_x : x[8192,512] -> A1 bf16 [8192,1536]
//   2) repack_b1 : Wq,Wv -> B1 bf16 [1024,1536] (row n = output col, K-major)
//      repack_b2 : Wup   -> B2 bf16 [512,1536]
//   3) gemm_mma  : QV[8192,1024] fp32 = A1 @ B1^T   (m16n8k16 bf16, fp32 acc)
//   4) band_attn : QV -> A2 bf16 [8192,1536] (split fused into epilogue)
//   5) gemm_mma  : out[8192,512] = A2 @ B2^T
// ----------------------------------------------------------------------------

#define M_ROWS   8192
#define N_SEQ    4096
#define NHEAD    8
#define CONTEXT  10
#define KBIG     1536
#define NCHUNK   24          // 1536 / 64

__device__ __nv_bfloat16 g_A1[M_ROWS * KBIG];
__device__ __nv_bfloat16 g_A2[M_ROWS * KBIG];
__device__ __nv_bfloat16 g_B1[1024 * KBIG];
__device__ __nv_bfloat16 g_B2[512  * KBIG];
__device__ float         g_QV[M_ROWS * 1024];

// ============================ PTX helpers ====================================
__device__ __forceinline__ uint32_t smem_u32(const void* p) {
    uint32_t a;
    asm("{ .reg .u64 t; cvta.to.shared.u64 t, %1; cvt.u32.u64 %0, t; }"
        : "=r"(a) : "l"(p));
    return a;
}
__device__ __forceinline__ void cp_async16(uint32_t dst, const void* src) {
    asm volatile("cp.async.cg.shared.global [%0], [%1], 16;"
                 :: "r"(dst), "l"(src) : "memory");
}
__device__ __forceinline__ void cp_commit() {
    asm volatile("cp.async.commit_group;" ::: "memory");
}
template <int N>
__device__ __forceinline__ void cp_wait() {
    asm volatile("cp.async.wait_group %0;" :: "n"(N) : "memory");
}
__device__ __forceinline__ void ldm_x4(uint32_t& r0, uint32_t& r1,
                                       uint32_t& r2, uint32_t& r3, uint32_t a) {
    asm volatile("ldmatrix.sync.aligned.m8n8.x4.shared.b16 {%0,%1,%2,%3}, [%4];"
                 : "=r"(r0), "=r"(r1), "=r"(r2), "=r"(r3) : "r"(a));
}
__device__ __forceinline__ void mma16816(float* c, const uint32_t* a,
                                         const uint32_t* b) {
    asm volatile(
        "mma.sync.aligned.m16n8k16.row.col.f32.bf16.bf16.f32 "
        "{%0,%1,%2,%3}, {%4,%5,%6,%7}, {%8,%9}, {%0,%1,%2,%3};"
        : "+f"(c[0]), "+f"(c[1]), "+f"(c[2]), "+f"(c[3])
        : "r"(a[0]), "r"(a[1]), "r"(a[2]), "r"(a[3]), "r"(b[0]), "r"(b[1]));
}

// ======================= conversion / repack kernels =========================
__device__ __forceinline__ void split_store(__nv_bfloat16* base, int k,
                                            int stride3, float v) {
    __nv_bfloat16 h = __float2bfloat16(v);
    __nv_bfloat16 l = __float2bfloat16(v - __bfloat162float(h));
    base[k]               = h;
    base[k + stride3]     = l;
    base[k + 2 * stride3] = h;
}

__global__ void convert_x(const float* __restrict__ x,
                          __nv_bfloat16* __restrict__ A1) {
    int idx = blockIdx.x * 256 + threadIdx.x;     // [0, 8192*512)
    int row = idx >> 9, k = idx & 511;
    split_store(A1 + (size_t)row * KBIG, k, 512, x[idx]);
}

__global__ void repack_b1(const float* __restrict__ Wq,
                          const float* __restrict__ Wv,
                          __nv_bfloat16* __restrict__ B1) {
    int idx = blockIdx.x * 256 + threadIdx.x;     // [0, 1024*512)
    int n = idx >> 9, d = idx & 511;
    float w;
    if (n < 512) {
        int h = n >> 6, k2 = n & 63;
        w = Wq[h * (512 * 64) + d * 64 + k2];
    } else {
        int nn = n - 512, h = nn >> 6, k2 = nn & 63;
        w = Wv[h * (512 * 64) + d * 64 + k2];
    }
    // B swaps the roles: [hi | hi | lo]
    __nv_bfloat16 hh = __float2bfloat16(w);
    __nv_bfloat16 ll = __float2bfloat16(w - __bfloat162float(hh));
    __nv_bfloat16* p = B1 + (size_t)n * KBIG;
    p[d] = hh; p[d + 512] = hh; p[d + 1024] = ll;
}

__global__ void repack_b2(const float* __restrict__ Wup,
                          __nv_bfloat16* __restrict__ B2) {
    int idx = blockIdx.x * 256 + threadIdx.x;     // [0, 512*512)
    int n = idx >> 9, d = idx & 511;
    float w = Wup[d * 512 + n];
    __nv_bfloat16 hh = __float2bfloat16(w);
    __nv_bfloat16 ll = __float2bfloat16(w - __bfloat162float(hh));
    __nv_bfloat16* p = B2 + (size_t)n * KBIG;
    p[d] = hh; p[d + 512] = hh; p[d + 1024] = ll;
}

// ====================== HMMA bf16 GEMM =======================================
// C[M,N] fp32 = A[M,1536] @ B[N,1536]^T. 128x128 CTA tile, 256 threads,
// 8 warps of 64x32. k-chunks of 64, cp.async double buffer, SW128 swizzle.
__device__ __forceinline__ void load_tiles(uint32_t sA, uint32_t sB,
                                           const __nv_bfloat16* __restrict__ A,
                                           const __nv_bfloat16* __restrict__ B,
                                           int bm, int bn, int ck, int tid) {
    const __nv_bfloat16* Ab = A + (size_t)bm * KBIG + ck * 64;
    const __nv_bfloat16* Bb = B + (size_t)bn * KBIG + ck * 64;
    #pragma unroll
    for (int g = 0; g < 4; g++) {
        int id  = g * 256 + tid;         // 0..1023 granules of 16B
        int row = id >> 3;               // 0..127
        int c16 = id & 7;                // 0..7
        uint32_t sw = row * 128 + ((c16 * 16) ^ ((row & 7) * 16));
        cp_async16(sA + sw, Ab + (size_t)row * KBIG + c16 * 8);
        cp_async16(sB + sw, Bb + (size_t)row * KBIG + c16 * 8);
    }
}

__global__ __launch_bounds__(256)
void gemm_mma(const __nv_bfloat16* __restrict__ A,
              const __nv_bfloat16* __restrict__ B,
              float* __restrict__ C, int N) {
    extern __shared__ char smem[];
    uint32_t sb = smem_u32(smem);
    // buffers: A0, B0, A1, B1 each 128*128B = 16KB
    uint32_t SA[2] = {sb, sb + 32768};
    uint32_t SB[2] = {sb + 16384, sb + 49152};

    const int tid  = threadIdx.x;
    const int lane = tid & 31;
    const int warp = tid >> 5;
    const int wm   = (warp >> 2) * 64;   // 0 or 64
    const int wn   = (warp & 3) * 32;    // 0,32,64,96
    const int bm   = blockIdx.y * 128, bn = blockIdx.x * 128;

    // ldmatrix lane address components (within an m16k16 / n16k16 block):
    // lane l: matrix j = l>>3; row-in-16 = (l&7) + ((j&1)<<3); kblock = (j>>1)*8
    const int fr = (lane & 7) + ((lane >> 3) & 1) * 8;   // row within 16
    const int fk = (lane >> 4) * 16;                     // byte offset of k-half

    float acc[4][4][4];
    #pragma unroll
    for (int i = 0; i < 4; i++)
        #pragma unroll
        for (int j = 0; j < 4; j++)
            #pragma unroll
            for (int q = 0; q < 4; q++) acc[i][j][q] = 0.f;

    load_tiles(SA[0], SB[0], A, B, bm, bn, 0, tid); cp_commit();
    load_tiles(SA[1], SB[1], A, B, bm, bn, 1, tid); cp_commit();

    #pragma unroll 1
    for (int c = 0; c < NCHUNK; c++) {
        uint32_t sA = SA[c & 1], sBt = SB[c & 1];

        if (c == NCHUNK - 1) cp_wait<0>(); else cp_wait<1>();
        __syncthreads();

        #pragma unroll
        for (int ks = 0; ks < 4; ks++) {
            const int k0b = ks * 32;                 // byte offset of k16 step
            uint32_t af[4][4], bf[4][2];
            #pragma unroll
            for (int mi = 0; mi < 4; mi++) {
                int r = wm + mi * 16 + fr;
                uint32_t addr = sA + r * 128 + ((k0b + fk) ^ ((r & 7) * 16));
                ldm_x4(af[mi][0], af[mi][1], af[mi][2], af[mi][3], addr);
            }
            #pragma unroll
            for (int ni = 0; ni < 2; ni++) {
                int r = wn + ni * 16 + fr;
                uint32_t addr = sBt + r * 128 + ((k0b + fk) ^ ((r & 7) * 16));
                uint32_t r0, r1, r2, r3;
                ldm_x4(r0, r1, r2, r3, addr);
                bf[2 * ni][0]     = r0; bf[2 * ni][1]     = r2;
                bf[2 * ni + 1][0] = r1; bf[2 * ni + 1][1] = r3;
            }
            #pragma unroll
            for (int mi = 0; mi < 4; mi++)
                #pragma unroll
                for (int nj = 0; nj < 4; nj++)
                    mma16816(acc[mi][nj], af[mi], bf[nj]);
        }

        __syncthreads();
        if (c + 2 < NCHUNK) {
            load_tiles(sA, sBt, A, B, bm, bn, c + 2, tid);
            cp_commit();
        }
    }

    // epilogue: thread t of each warp owns rows (t/4, t/4+8), cols 2*(t%4)
    const int er = lane >> 2;
    const int ec = (lane & 3) * 2;
    #pragma unroll
    for (int mi = 0; mi < 4; mi++) {
        #pragma unroll
        for (int nj = 0; nj < 4; nj++) {
            int row = bm + wm + mi * 16 + er;
            int col = bn + wn + nj * 8 + ec;
            *(float2*)(C + (size_t)row * N + col) =
                make_float2(acc[mi][nj][0], acc[mi][nj][1]);
            *(float2*)(C + (size_t)(row + 8) * N + col) =
                make_float2(acc[mi][nj][2], acc[mi][nj][3]);
        }
    }
}

// ============================ band attention =================================
#define TILE_I 64
#define VROWS  (TILE_I + 2 * CONTEXT)   // 84
#define PITCH  65

__global__ __launch_bounds__(256)
void band_attn_kernel(const float* __restrict__ QV,
                      __nv_bfloat16* __restrict__ A2) {
    __shared__ float Vs[VROWS * PITCH];
    __shared__ float Qs[TILE_I * PITCH];

    const int bx   = blockIdx.x;
    const int tile = bx & 63;
    const int h    = (bx >> 6) & 7;
    const int b    = bx >> 9;
    const int i0   = tile * TILE_I;
    const int tid  = threadIdx.x;
    const int lane = tid & 31;
    const int warp = tid >> 5;

    for (int idx = tid; idx < VROWS * 16; idx += 256) {
        int r  = idx >> 4;
        int kq = idx & 15;
        int j  = i0 - CONTEXT + r;
        float4 v = make_float4(0.f, 0.f, 0.f, 0.f);
        if (j >= 0 && j < N_SEQ)
            v = *(const float4*)(QV + (b * N_SEQ + j) * 1024 + 512 + h * 64 + kq * 4);
        float* p = &Vs[r * PITCH + kq * 4];
        p[0] = v.x; p[1] = v.y; p[2] = v.z; p[3] = v.w;
    }
    for (int idx = tid; idx < TILE_I * 16; idx += 256) {
        int r  = idx >> 4;
        int kq = idx & 15;
        float4 v = *(const float4*)(QV + (b * N_SEQ + i0 + r) * 1024 + h * 64 + kq * 4);
        float* p = &Qs[r * PITCH + kq * 4];
        p[0] = v.x; p[1] = v.y; p[2] = v.z; p[3] = v.w;
    }
    __syncthreads();

    for (int t = 0; t < 8; t++) {
        int il = warp * 8 + t;
        int i  = i0 + il;

        float s = -1e30f;
        if (lane < 21 && lane != CONTEXT) {
            int j = i + lane - CONTEXT;
            if (j >= 0 && j < N_SEQ) {
                const float* qp = &Qs[il * PITCH];
                const float* vp = &Vs[(il + lane) * PITCH];
                float acc = 0.f;
                #pragma unroll
                for (int k = 0; k < 64; k++)
                    acc += qp[k] * vp[k];
                s = acc * (1.0f / 16.0f);
            }
        }

        float mx = s;
        #pragma unroll
        for (int o = 16; o > 0; o >>= 1)
            mx = fmaxf(mx, __shfl_xor_sync(0xffffffffu, mx, o));
        float p = __expf(s - mx);
        float sum = p;
        #pragma unroll
        for (int o = 16; o > 0; o >>= 1)
            sum += __shfl_xor_sync(0xffffffffu, sum, o);
        float w = p / sum;

        float a0 = 0.f, a1 = 0.f;
        #pragma unroll
        for (int jj = 0; jj < 21; jj++) {
            float wj = __shfl_sync(0xffffffffu, w, jj);
            const float* vp = &Vs[(il + jj) * PITCH];
            a0 += wj * vp[lane];
            a1 += wj * vp[lane + 32];
        }
        __nv_bfloat16* cp = A2 + (size_t)(b * N_SEQ + i) * KBIG + h * 64;
        split_store(cp, lane,      512, a0);
        split_store(cp, lane + 32, 512, a1);
    }
}

// ================================ launch =====================================
extern "C" void kernel_launch(void* const* d_in, const int* in_sizes, int n_in,
                              void* d_out, int out_size) {
    const float* x   = (const float*)d_in[0];
    const float* Wq  = (const float*)d_in[1];
    const float* Wv  = (const float*)d_in[2];
    const float* Wup = (const float*)d_in[3];
    float* out = (float*)d_out;

    __nv_bfloat16 *a1, *a2, *b1, *b2;
    float *qv;
    cudaGetSymbolAddress((void**)&a1, g_A1);
    cudaGetSymbolAddress((void**)&a2, g_A2);
    cudaGetSymbolAddress((void**)&b1, g_B1);
    cudaGetSymbolAddress((void**)&b2, g_B2);
    cudaGetSymbolAddress((void**)&qv, g_QV);

    const int SMEM_BYTES = 65536;
    cudaFuncSetAttribute(gemm_mma, cudaFuncAttributeMaxDynamicSharedMemorySize,
                         SMEM_BYTES);

    convert_x<<<(M_ROWS * 512) / 256, 256>>>(x, a1);
    repack_b1<<<(1024 * 512) / 256, 256>>>(Wq, Wv, b1);
    repack_b2<<<(512 * 512) / 256, 256>>>(Wup, b2);

    gemm_mma<<<dim3(1024 / 128, M_ROWS / 128), 256, SMEM_BYTES>>>(a1, b1, qv, 1024);
    band_attn_kernel<<<2 * NHEAD * (N_SEQ / TILE_I), 256>>>(qv, a2);
    gemm_mma<<<dim3(512 / 128, M_ROWS / 128), 256, SMEM_BYTES>>>(a2, b2, out, 512);
}

// round 7
// speedup vs baseline: 1.9084x; 1.0518x over previous
#include <cuda_runtime.h>
#include <cuda_bf16.h>
#include <cstdint>

// ----------------------------------------------------------------------------
// MultiHeadAttn via bf16 split + mma.sync (HMMA, family-target safe):
//   fp32 -> (hi, lo) bf16 split; GEMMs run as bf16 K'=1536 = [hi|lo|hi]x[hi|hi|lo]
//   1) convert_x : x[8192,512] -> A1 bf16 [8192,1536]
//   2) repack_b1 : Wq,Wv -> B1 bf16 [1024,1536];  repack_b2 : Wup -> B2 [512,1536]
//   3) gemm_mma  : QV[8192,1024] fp32 = A1 @ B1^T  (64x64 warp tile, 3-stage)
//   4) band_attn : QV -> A2 bf16 [8192,1536] (float4 smem reads, split epilogue)
//   5) gemm_mma  : out[8192,512] = A2 @ B2^T
// ----------------------------------------------------------------------------

#define M_ROWS   8192
#define N_SEQ    4096
#define NHEAD    8
#define CONTEXT  10
#define KBIG     1536
#define NCHUNK   24          // 1536 / 64

__device__ __nv_bfloat16 g_A1[M_ROWS * KBIG];
__device__ __nv_bfloat16 g_A2[M_ROWS * KBIG];
__device__ __nv_bfloat16 g_B1[1024 * KBIG];
__device__ __nv_bfloat16 g_B2[512  * KBIG];
__device__ float         g_QV[M_ROWS * 1024];

// ============================ PTX helpers ====================================
__device__ __forceinline__ uint32_t smem_u32(const void* p) {
    uint32_t a;
    asm("{ .reg .u64 t; cvta.to.shared.u64 t, %1; cvt.u32.u64 %0, t; }"
        : "=r"(a) : "l"(p));
    return a;
}
__device__ __forceinline__ void cp_async16(uint32_t dst, const void* src) {
    asm volatile("cp.async.cg.shared.global [%0], [%1], 16;"
                 :: "r"(dst), "l"(src) : "memory");
}
__device__ __forceinline__ void cp_commit() {
    asm volatile("cp.async.commit_group;" ::: "memory");
}
template <int N>
__device__ __forceinline__ void cp_wait() {
    asm volatile("cp.async.wait_group %0;" :: "n"(N) : "memory");
}
__device__ __forceinline__ void ldm_x4(uint32_t& r0, uint32_t& r1,
                                       uint32_t& r2, uint32_t& r3, uint32_t a) {
    asm volatile("ldmatrix.sync.aligned.m8n8.x4.shared.b16 {%0,%1,%2,%3}, [%4];"
                 : "=r"(r0), "=r"(r1), "=r"(r2), "=r"(r3) : "r"(a));
}
__device__ __forceinline__ void mma16816(float* c, const uint32_t* a,
                                         const uint32_t* b) {
    asm volatile(
        "mma.sync.aligned.m16n8k16.row.col.f32.bf16.bf16.f32 "
        "{%0,%1,%2,%3}, {%4,%5,%6,%7}, {%8,%9}, {%0,%1,%2,%3};"
        : "+f"(c[0]), "+f"(c[1]), "+f"(c[2]), "+f"(c[3])
        : "r"(a[0]), "r"(a[1]), "r"(a[2]), "r"(a[3]), "r"(b[0]), "r"(b[1]));
}

// ======================= conversion / repack kernels =========================
__device__ __forceinline__ void split_store(__nv_bfloat16* base, int k,
                                            int stride3, float v) {
    __nv_bfloat16 h = __float2bfloat16(v);
    __nv_bfloat16 l = __float2bfloat16(v - __bfloat162float(h));
    base[k]               = h;
    base[k + stride3]     = l;
    base[k + 2 * stride3] = h;
}

__global__ void convert_x(const float* __restrict__ x,
                          __nv_bfloat16* __restrict__ A1) {
    int idx = blockIdx.x * 256 + threadIdx.x;     // [0, 8192*512)
    int row = idx >> 9, k = idx & 511;
    split_store(A1 + (size_t)row * KBIG, k, 512, x[idx]);
}

__global__ void repack_b1(const float* __restrict__ Wq,
                          const float* __restrict__ Wv,
                          __nv_bfloat16* __restrict__ B1) {
    int idx = blockIdx.x * 256 + threadIdx.x;     // [0, 1024*512)
    int n = idx >> 9, d = idx & 511;
    float w;
    if (n < 512) {
        int h = n >> 6, k2 = n & 63;
        w = Wq[h * (512 * 64) + d * 64 + k2];
    } else {
        int nn = n - 512, h = nn >> 6, k2 = nn & 63;
        w = Wv[h * (512 * 64) + d * 64 + k2];
    }
    // B side: [hi | hi | lo]
    __nv_bfloat16 hh = __float2bfloat16(w);
    __nv_bfloat16 ll = __float2bfloat16(w - __bfloat162float(hh));
    __nv_bfloat16* p = B1 + (size_t)n * KBIG;
    p[d] = hh; p[d + 512] = hh; p[d + 1024] = ll;
}

__global__ void repack_b2(const float* __restrict__ Wup,
                          __nv_bfloat16* __restrict__ B2) {
    int idx = blockIdx.x * 256 + threadIdx.x;     // [0, 512*512)
    int n = idx >> 9, d = idx & 511;
    float w = Wup[d * 512 + n];
    __nv_bfloat16 hh = __float2bfloat16(w);
    __nv_bfloat16 ll = __float2bfloat16(w - __bfloat162float(hh));
    __nv_bfloat16* p = B2 + (size_t)n * KBIG;
    p[d] = hh; p[d + 512] = hh; p[d + 1024] = ll;
}

// ====================== HMMA bf16 GEMM =======================================
// C[M,N] fp32 = A[M,1536] @ B[N,1536]^T. 128x128 CTA tile, 128 threads,
// 4 warps of 64x64, k-chunks of 64, 3-stage cp.async, SW128 swizzle.
__device__ __forceinline__ void load_tiles(uint32_t sA, uint32_t sB,
                                           const __nv_bfloat16* __restrict__ A,
                                           const __nv_bfloat16* __restrict__ B,
                                           int bm, int bn, int ck, int tid) {
    const __nv_bfloat16* Ab = A + (size_t)bm * KBIG + ck * 64;
    const __nv_bfloat16* Bb = B + (size_t)bn * KBIG + ck * 64;
    #pragma unroll
    for (int g = 0; g < 8; g++) {
        int id  = g * 128 + tid;         // 0..1023 granules of 16B
        int row = id >> 3;               // 0..127
        int c16 = id & 7;                // 0..7
        uint32_t sw = row * 128 + ((c16 * 16) ^ ((row & 7) * 16));
        cp_async16(sA + sw, Ab + (size_t)row * KBIG + c16 * 8);
        cp_async16(sB + sw, Bb + (size_t)row * KBIG + c16 * 8);
    }
}

__global__ __launch_bounds__(128)
void gemm_mma(const __nv_bfloat16* __restrict__ A,
              const __nv_bfloat16* __restrict__ B,
              float* __restrict__ C, int N) {
    extern __shared__ char smem[];
    uint32_t sb = smem_u32(smem);
    // 3 stages x (A 16KB + B 16KB)
    uint32_t SA[3] = {sb, sb + 32768, sb + 65536};
    uint32_t SB[3] = {sb + 16384, sb + 49152, sb + 81920};

    const int tid  = threadIdx.x;
    const int lane = tid & 31;
    const int warp = tid >> 5;
    const int wm   = (warp >> 1) * 64;   // 0 or 64
    const int wn   = (warp & 1) * 64;    // 0 or 64
    const int bm   = blockIdx.y * 128, bn = blockIdx.x * 128;

    const int fr = (lane & 7) + ((lane >> 3) & 1) * 8;   // row within 16
    const int fk = (lane >> 4) * 16;                     // byte offset of k-half

    float acc[4][8][4];
    #pragma unroll
    for (int i = 0; i < 4; i++)
        #pragma unroll
        for (int j = 0; j < 8; j++)
            #pragma unroll
            for (int q = 0; q < 4; q++) acc[i][j][q] = 0.f;

    load_tiles(SA[0], SB[0], A, B, bm, bn, 0, tid); cp_commit();
    load_tiles(SA[1], SB[1], A, B, bm, bn, 1, tid); cp_commit();

    #pragma unroll 1
    for (int c = 0; c < NCHUNK; c++) {
        const int s = c % 3;
        uint32_t sA = SA[s], sBt = SB[s];

        if (c == NCHUNK - 1) cp_wait<0>(); else cp_wait<1>();
        __syncthreads();     // chunk c visible; all reads of stage (c+2)%3 done

        if (c + 2 < NCHUNK) {
            const int s2 = (c + 2) % 3;
            load_tiles(SA[s2], SB[s2], A, B, bm, bn, c + 2, tid);
            cp_commit();
        }

        #pragma unroll
        for (int ks = 0; ks < 4; ks++) {
            const int k0b = ks * 32;                 // byte offset of k16 step
            uint32_t af[4][4], bf[8][2];
            #pragma unroll
            for (int mi = 0; mi < 4; mi++) {
                int r = wm + mi * 16 + fr;
                uint32_t addr = sA + r * 128 + ((k0b + fk) ^ ((r & 7) * 16));
                ldm_x4(af[mi][0], af[mi][1], af[mi][2], af[mi][3], addr);
            }
            #pragma unroll
            for (int ni = 0; ni < 4; ni++) {
                int r = wn + ni * 16 + fr;
                uint32_t addr = sBt + r * 128 + ((k0b + fk) ^ ((r & 7) * 16));
                uint32_t r0, r1, r2, r3;
                ldm_x4(r0, r1, r2, r3, addr);
                bf[2 * ni][0]     = r0; bf[2 * ni][1]     = r2;
                bf[2 * ni + 1][0] = r1; bf[2 * ni + 1][1] = r3;
            }
            #pragma unroll
            for (int mi = 0; mi < 4; mi++)
                #pragma unroll
                for (int nj = 0; nj < 8; nj++)
                    mma16816(acc[mi][nj], af[mi], bf[nj]);
        }
    }

    // epilogue: thread t of each warp owns rows (t/4, t/4+8), cols 2*(t%4)
    const int er = lane >> 2;
    const int ec = (lane & 3) * 2;
    #pragma unroll
    for (int mi = 0; mi < 4; mi++) {
        #pragma unroll
        for (int nj = 0; nj < 8; nj++) {
            int row = bm + wm + mi * 16 + er;
            int col = bn + wn + nj * 8 + ec;
            *(float2*)(C + (size_t)row * N + col) =
                make_float2(acc[mi][nj][0], acc[mi][nj][1]);
            *(float2*)(C + (size_t)(row + 8) * N + col) =
                make_float2(acc[mi][nj][2], acc[mi][nj][3]);
        }
    }
}

// ============================ band attention =================================
// PITCH=68: float4-aligned rows (272B), bank stride 68%32=4 -> conflict-free
// float4 phase (per-8-lane phases see distinct banks) and scalar phase C.
#define TILE_I 64
#define VROWS  (TILE_I + 2 * CONTEXT)   // 84
#define PITCH  68

__global__ __launch_bounds__(256)
void band_attn_kernel(const float* __restrict__ QV,
                      __nv_bfloat16* __restrict__ A2) {
    __shared__ float Vs[VROWS * PITCH];
    __shared__ float Qs[TILE_I * PITCH];

    const int bx   = blockIdx.x;
    const int tile = bx & 63;
    const int h    = (bx >> 6) & 7;
    const int b    = bx >> 9;
    const int i0   = tile * TILE_I;
    const int tid  = threadIdx.x;
    const int lane = tid & 31;
    const int warp = tid >> 5;

    for (int idx = tid; idx < VROWS * 16; idx += 256) {
        int r  = idx >> 4;
        int kq = idx & 15;
        int j  = i0 - CONTEXT + r;
        float4 v = make_float4(0.f, 0.f, 0.f, 0.f);
        if (j >= 0 && j < N_SEQ)
            v = *(const float4*)(QV + (b * N_SEQ + j) * 1024 + 512 + h * 64 + kq * 4);
        *(float4*)&Vs[r * PITCH + kq * 4] = v;
    }
    for (int idx = tid; idx < TILE_I * 16; idx += 256) {
        int r  = idx >> 4;
        int kq = idx & 15;
        float4 v = *(const float4*)(QV + (b * N_SEQ + i0 + r) * 1024 + h * 64 + kq * 4);
        *(float4*)&Qs[r * PITCH + kq * 4] = v;
    }
    __syncthreads();

    for (int t = 0; t < 8; t++) {
        int il = warp * 8 + t;
        int i  = i0 + il;

        // phase A: lane L -> offset d = L-10, score = Q_i . V_{i+d} / 16
        float s = -1e30f;
        if (lane < 21 && lane != CONTEXT) {
            int j = i + lane - CONTEXT;
            if (j >= 0 && j < N_SEQ) {
                const float4* qp = (const float4*)&Qs[il * PITCH];
                const float4* vp = (const float4*)&Vs[(il + lane) * PITCH];
                float acc = 0.f;
                #pragma unroll
                for (int k = 0; k < 16; k++) {
                    float4 a = qp[k], v = vp[k];
                    acc += a.x * v.x + a.y * v.y + a.z * v.z + a.w * v.w;
                }
                s = acc * (1.0f / 16.0f);
            }
        }

        // phase B: softmax across band lanes
        float mx = s;
        #pragma unroll
        for (int o = 16; o > 0; o >>= 1)
            mx = fmaxf(mx, __shfl_xor_sync(0xffffffffu, mx, o));
        float p = __expf(s - mx);
        float sum = p;
        #pragma unroll
        for (int o = 16; o > 0; o >>= 1)
            sum += __shfl_xor_sync(0xffffffffu, sum, o);
        float w = p / sum;

        // phase C: C_i[k] = sum_j w_j V_j[k]; lane handles k=lane, lane+32
        float a0 = 0.f, a1 = 0.f;
        #pragma unroll
        for (int jj = 0; jj < 21; jj++) {
            float wj = __shfl_sync(0xffffffffu, w, jj);
            const float* vp = &Vs[(il + jj) * PITCH];
            a0 += wj * vp[lane];
            a1 += wj * vp[lane + 32];
        }
        __nv_bfloat16* cp = A2 + (size_t)(b * N_SEQ + i) * KBIG + h * 64;
        split_store(cp, lane,      512, a0);
        split_store(cp, lane + 32, 512, a1);
    }
}

// ================================ launch =====================================
extern "C" void kernel_launch(void* const* d_in, const int* in_sizes, int n_in,
                              void* d_out, int out_size) {
    const float* x   = (const float*)d_in[0];
    const float* Wq  = (const float*)d_in[1];
    const float* Wv  = (const float*)d_in[2];
    const float* Wup = (const float*)d_in[3];
    float* out = (float*)d_out;

    __nv_bfloat16 *a1, *a2, *b1, *b2;
    float *qv;
    cudaGetSymbolAddress((void**)&a1, g_A1);
    cudaGetSymbolAddress((void**)&a2, g_A2);
    cudaGetSymbolAddress((void**)&b1, g_B1);
    cudaGetSymbolAddress((void**)&b2, g_B2);
    cudaGetSymbolAddress((void**)&qv, g_QV);

    const int SMEM_BYTES = 98304;   // 3 stages x 32KB
    cudaFuncSetAttribute(gemm_mma, cudaFuncAttributeMaxDynamicSharedMemorySize,
                         SMEM_BYTES);

    convert_x<<<(M_ROWS * 512) / 256, 256>>>(x, a1);
    repack_b1<<<(1024 * 512) / 256, 256>>>(Wq, Wv, b1);
    repack_b2<<<(512 * 512) / 256, 256>>>(Wup, b2);

    gemm_mma<<<dim3(1024 / 128, M_ROWS / 128), 128, SMEM_BYTES>>>(a1, b1, qv, 1024);
    band_attn_kernel<<<2 * NHEAD * (N_SEQ / TILE_I), 256>>>(qv, a2);
    gemm_mma<<<dim3(512 / 128, M_ROWS / 128), 128, SMEM_BYTES>>>(a2, b2, out, 512);
}

// round 8
// speedup vs baseline: 2.5259x; 1.3236x over previous
#include <cuda_runtime.h>
#include <cuda_fp16.h>
#include <cstdint>

// ----------------------------------------------------------------------------
// MultiHeadAttn via fp16 2-term split + mma.sync:
//   A side exact: A' = [A_hi | A_lo] fp16 (K'=1024); B side hi-only, scaled 2^13.
//   GEMM: C = A' @ [B_hi | B_hi]^T * escale   (error ~2^-11 from dropped B_lo)
//   1) convert_x : x[8192,512] -> A1 fp16 [8192,1024]  (hi|lo)
//   2) repack_b  : Wq,Wv -> B1 fp16 [1024,512] (x8192); Wup -> B2 [512,512] (x8192)
//   3) gemm_mma  : QV[8192,1024] fp32 = A1 @ B1dup^T, escale=2^-13
//   4) band_attn : QV -> A2 fp16 [8192,1024] (C*256 hi|lo)
//   5) gemm_mma  : out[8192,512] = A2 @ B2dup^T, escale=2^-21
// ----------------------------------------------------------------------------

#define M_ROWS   8192
#define N_SEQ    4096
#define NHEAD    8
#define CONTEXT  10
#define KBIG     1024
#define NCHUNK   16          // 1024 / 64

#define BSCALE   8192.0f     // 2^13
#define CSCALE   256.0f      // 2^8

__device__ __half g_A1[M_ROWS * KBIG];
__device__ __half g_A2[M_ROWS * KBIG];
__device__ __half g_B1[1024 * 512];
__device__ __half g_B2[512  * 512];
__device__ float  g_QV[M_ROWS * 1024];

// ============================ PTX helpers ====================================
__device__ __forceinline__ uint32_t smem_u32(const void* p) {
    uint32_t a;
    asm("{ .reg .u64 t; cvta.to.shared.u64 t, %1; cvt.u32.u64 %0, t; }"
        : "=r"(a) : "l"(p));
    return a;
}
__device__ __forceinline__ void cp_async16(uint32_t dst, const void* src) {
    asm volatile("cp.async.cg.shared.global [%0], [%1], 16;"
                 :: "r"(dst), "l"(src) : "memory");
}
__device__ __forceinline__ void cp_commit() {
    asm volatile("cp.async.commit_group;" ::: "memory");
}
template <int N>
__device__ __forceinline__ void cp_wait() {
    asm volatile("cp.async.wait_group %0;" :: "n"(N) : "memory");
}
__device__ __forceinline__ void ldm_x4(uint32_t& r0, uint32_t& r1,
                                       uint32_t& r2, uint32_t& r3, uint32_t a) {
    asm volatile("ldmatrix.sync.aligned.m8n8.x4.shared.b16 {%0,%1,%2,%3}, [%4];"
                 : "=r"(r0), "=r"(r1), "=r"(r2), "=r"(r3) : "r"(a));
}
__device__ __forceinline__ void mma16816(float* c, const uint32_t* a,
                                         const uint32_t* b) {
    asm volatile(
        "mma.sync.aligned.m16n8k16.row.col.f32.f16.f16.f32 "
        "{%0,%1,%2,%3}, {%4,%5,%6,%7}, {%8,%9}, {%0,%1,%2,%3};"
        : "+f"(c[0]), "+f"(c[1]), "+f"(c[2]), "+f"(c[3])
        : "r"(a[0]), "r"(a[1]), "r"(a[2]), "r"(a[3]), "r"(b[0]), "r"(b[1]));
}

// ======================= conversion / repack kernels =========================
// x -> [hi | lo] fp16, 4 elements per thread, vectorized
__global__ void convert_x(const float* __restrict__ x,
                          __half* __restrict__ A1) {
    int idx = blockIdx.x * 256 + threadIdx.x;       // [0, 8192*128)
    int row = idx >> 7;
    int kq  = (idx & 127) * 4;
    float4 v = *(const float4*)(x + (size_t)row * 512 + kq);
    __half h0 = __float2half_rn(v.x), h1 = __float2half_rn(v.y);
    __half h2 = __float2half_rn(v.z), h3 = __float2half_rn(v.w);
    __half l0 = __float2half_rn(v.x - __half2float(h0));
    __half l1 = __float2half_rn(v.y - __half2float(h1));
    __half l2 = __float2half_rn(v.z - __half2float(h2));
    __half l3 = __float2half_rn(v.w - __half2float(h3));
    __half* p = A1 + (size_t)row * KBIG;
    __half2 hv[2] = {__halves2half2(h0, h1), __halves2half2(h2, h3)};
    __half2 lv[2] = {__halves2half2(l0, l1), __halves2half2(l2, l3)};
    *(uint2*)&p[kq]       = *(uint2*)hv;
    *(uint2*)&p[512 + kq] = *(uint2*)lv;
}

// fused weight repack: B1[1024,512] from Wq/Wv, B2[512,512] from Wup^T; x 2^13
__global__ void repack_b(const float* __restrict__ Wq,
                         const float* __restrict__ Wv,
                         const float* __restrict__ Wup,
                         __half* __restrict__ B1,
                         __half* __restrict__ B2) {
    int idx = blockIdx.x * 256 + threadIdx.x;       // [0, 1024*512 + 512*512)
    if (idx < 1024 * 512) {
        int n = idx >> 9, d = idx & 511;
        float w;
        if (n < 512) {
            int hh = n >> 6, k2 = n & 63;
            w = Wq[hh * (512 * 64) + d * 64 + k2];
        } else {
            int nn = n - 512, hh = nn >> 6, k2 = nn & 63;
            w = Wv[hh * (512 * 64) + d * 64 + k2];
        }
        B1[n * 512 + d] = __float2half_rn(w * BSCALE);
    } else {
        int i2 = idx - 1024 * 512;
        int n = i2 >> 9, d = i2 & 511;
        B2[n * 512 + d] = __float2half_rn(Wup[d * 512 + n] * BSCALE);
    }
}

// ====================== HMMA fp16 GEMM =======================================
// C[M,N] fp32 = escale * A[M,1024] @ [B|B][N,512dup]^T.
// 128x128 CTA tile, 128 threads, 4 warps of 64x64, 3-stage cp.async, SW128.
__device__ __forceinline__ void load_tiles(uint32_t sA, uint32_t sB,
                                           const __half* __restrict__ A,
                                           const __half* __restrict__ B,
                                           int bm, int bn, int ck, int tid) {
    const __half* Ab = A + (size_t)bm * KBIG + ck * 64;
    const __half* Bb = B + (size_t)bn * 512 + (ck & 7) * 64;  // B dup: hi twice
    #pragma unroll
    for (int g = 0; g < 8; g++) {
        int id  = g * 128 + tid;         // 0..1023 granules of 16B
        int row = id >> 3;               // 0..127
        int c16 = id & 7;                // 0..7
        uint32_t sw = row * 128 + ((c16 * 16) ^ ((row & 7) * 16));
        cp_async16(sA + sw, Ab + (size_t)row * KBIG + c16 * 8);
        cp_async16(sB + sw, Bb + (size_t)row * 512 + c16 * 8);
    }
}

__global__ __launch_bounds__(128)
void gemm_mma(const __half* __restrict__ A,
              const __half* __restrict__ B,
              float* __restrict__ C, int N, float escale) {
    extern __shared__ char smem[];
    uint32_t sb = smem_u32(smem);
    uint32_t SA[3] = {sb, sb + 32768, sb + 65536};
    uint32_t SB[3] = {sb + 16384, sb + 49152, sb + 81920};

    const int tid  = threadIdx.x;
    const int lane = tid & 31;
    const int warp = tid >> 5;
    const int wm   = (warp >> 1) * 64;
    const int wn   = (warp & 1) * 64;
    const int bm   = blockIdx.y * 128, bn = blockIdx.x * 128;

    const int fr = (lane & 7) + ((lane >> 3) & 1) * 8;
    const int fk = (lane >> 4) * 16;

    float acc[4][8][4];
    #pragma unroll
    for (int i = 0; i < 4; i++)
        #pragma unroll
        for (int j = 0; j < 8; j++)
            #pragma unroll
            for (int q = 0; q < 4; q++) acc[i][j][q] = 0.f;

    load_tiles(SA[0], SB[0], A, B, bm, bn, 0, tid); cp_commit();
    load_tiles(SA[1], SB[1], A, B, bm, bn, 1, tid); cp_commit();

    #pragma unroll 1
    for (int c = 0; c < NCHUNK; c++) {
        const int s = c % 3;
        uint32_t sA = SA[s], sBt = SB[s];

        if (c == NCHUNK - 1) cp_wait<0>(); else cp_wait<1>();
        __syncthreads();

        if (c + 2 < NCHUNK) {
            const int s2 = (c + 2) % 3;
            load_tiles(SA[s2], SB[s2], A, B, bm, bn, c + 2, tid);
            cp_commit();
        }

        #pragma unroll
        for (int ks = 0; ks < 4; ks++) {
            const int k0b = ks * 32;
            uint32_t af[4][4], bf[8][2];
            #pragma unroll
            for (int mi = 0; mi < 4; mi++) {
                int r = wm + mi * 16 + fr;
                uint32_t addr = sA + r * 128 + ((k0b + fk) ^ ((r & 7) * 16));
                ldm_x4(af[mi][0], af[mi][1], af[mi][2], af[mi][3], addr);
            }
            #pragma unroll
            for (int ni = 0; ni < 4; ni++) {
                int r = wn + ni * 16 + fr;
                uint32_t addr = sBt + r * 128 + ((k0b + fk) ^ ((r & 7) * 16));
                uint32_t r0, r1, r2, r3;
                ldm_x4(r0, r1, r2, r3, addr);
                bf[2 * ni][0]     = r0; bf[2 * ni][1]     = r2;
                bf[2 * ni + 1][0] = r1; bf[2 * ni + 1][1] = r3;
            }
            #pragma unroll
            for (int mi = 0; mi < 4; mi++)
                #pragma unroll
                for (int nj = 0; nj < 8; nj++)
                    mma16816(acc[mi][nj], af[mi], bf[nj]);
        }
    }

    const int er = lane >> 2;
    const int ec = (lane & 3) * 2;
    #pragma unroll
    for (int mi = 0; mi < 4; mi++) {
        #pragma unroll
        for (int nj = 0; nj < 8; nj++) {
            int row = bm + wm + mi * 16 + er;
            int col = bn + wn + nj * 8 + ec;
            *(float2*)(C + (size_t)row * N + col) =
                make_float2(acc[mi][nj][0] * escale, acc[mi][nj][1] * escale);
            *(float2*)(C + (size_t)(row + 8) * N + col) =
                make_float2(acc[mi][nj][2] * escale, acc[mi][nj][3] * escale);
        }
    }
}

// ============================ band attention =================================
#define TILE_I 64
#define VROWS  (TILE_I + 2 * CONTEXT)   // 84
#define PITCH  68

__global__ __launch_bounds__(256)
void band_attn_kernel(const float* __restrict__ QV,
                      __half* __restrict__ A2) {
    __shared__ float Vs[VROWS * PITCH];
    __shared__ float Qs[TILE_I * PITCH];

    const int bx   = blockIdx.x;
    const int tile = bx & 63;
    const int hd   = (bx >> 6) & 7;
    const int b    = bx >> 9;
    const int i0   = tile * TILE_I;
    const int tid  = threadIdx.x;
    const int lane = tid & 31;
    const int warp = tid >> 5;

    for (int idx = tid; idx < VROWS * 16; idx += 256) {
        int r  = idx >> 4;
        int kq = idx & 15;
        int j  = i0 - CONTEXT + r;
        float4 v = make_float4(0.f, 0.f, 0.f, 0.f);
        if (j >= 0 && j < N_SEQ)
            v = *(const float4*)(QV + (b * N_SEQ + j) * 1024 + 512 + hd * 64 + kq * 4);
        *(float4*)&Vs[r * PITCH + kq * 4] = v;
    }
    for (int idx = tid; idx < TILE_I * 16; idx += 256) {
        int r  = idx >> 4;
        int kq = idx & 15;
        float4 v = *(const float4*)(QV + (b * N_SEQ + i0 + r) * 1024 + hd * 64 + kq * 4);
        *(float4*)&Qs[r * PITCH + kq * 4] = v;
    }
    __syncthreads();

    for (int t = 0; t < 8; t++) {
        int il = warp * 8 + t;
        int i  = i0 + il;

        // phase A: lane L -> offset d = L-10, score = Q_i . V_{i+d} / 16
        float s = -1e30f;
        if (lane < 21 && lane != CONTEXT) {
            int j = i + lane - CONTEXT;
            if (j >= 0 && j < N_SEQ) {
                const float4* qp = (const float4*)&Qs[il * PITCH];
                const float4* vp = (const float4*)&Vs[(il + lane) * PITCH];
                float acc = 0.f;
                #pragma unroll
                for (int k = 0; k < 16; k++) {
                    float4 a = qp[k], v = vp[k];
                    acc += a.x * v.x + a.y * v.y + a.z * v.z + a.w * v.w;
                }
                s = acc * (1.0f / 16.0f);
            }
        }

        // phase B: softmax across band lanes
        float mx = s;
        #pragma unroll
        for (int o = 16; o > 0; o >>= 1)
            mx = fmaxf(mx, __shfl_xor_sync(0xffffffffu, mx, o));
        float p = __expf(s - mx);
        float sum = p;
        #pragma unroll
        for (int o = 16; o > 0; o >>= 1)
            sum += __shfl_xor_sync(0xffffffffu, sum, o);
        float w = p / sum;

        // phase C: lane handles k = 2*lane, 2*lane+1 (float2 smem reads)
        float a0 = 0.f, a1 = 0.f;
        #pragma unroll
        for (int jj = 0; jj < 21; jj++) {
            float wj = __shfl_sync(0xffffffffu, w, jj);
            float2 vv = *(const float2*)&Vs[(il + jj) * PITCH + 2 * lane];
            a0 += wj * vv.x;
            a1 += wj * vv.y;
        }
        // scaled split store: C*256 -> [hi | lo] half2
        float s0 = a0 * CSCALE, s1 = a1 * CSCALE;
        __half h0 = __float2half_rn(s0), h1 = __float2half_rn(s1);
        __half l0 = __float2half_rn(s0 - __half2float(h0));
        __half l1 = __float2half_rn(s1 - __half2float(h1));
        __half* cp = A2 + (size_t)(b * N_SEQ + i) * KBIG + hd * 64;
        *(__half2*)&cp[2 * lane]       = __halves2half2(h0, h1);
        *(__half2*)&cp[512 + 2 * lane] = __halves2half2(l0, l1);
    }
}

// ================================ launch =====================================
extern "C" void kernel_launch(void* const* d_in, const int* in_sizes, int n_in,
                              void* d_out, int out_size) {
    const float* x   = (const float*)d_in[0];
    const float* Wq  = (const float*)d_in[1];
    const float* Wv  = (const float*)d_in[2];
    const float* Wup = (const float*)d_in[3];
    float* out = (float*)d_out;

    __half *a1, *a2, *b1, *b2;
    float *qv;
    cudaGetSymbolAddress((void**)&a1, g_A1);
    cudaGetSymbolAddress((void**)&a2, g_A2);
    cudaGetSymbolAddress((void**)&b1, g_B1);
    cudaGetSymbolAddress((void**)&b2, g_B2);
    cudaGetSymbolAddress((void**)&qv, g_QV);

    const int SMEM_BYTES = 98304;   // 3 stages x 32KB
    cudaFuncSetAttribute(gemm_mma, cudaFuncAttributeMaxDynamicSharedMemorySize,
                         SMEM_BYTES);

    convert_x<<<(M_ROWS * 128) / 256, 256>>>(x, a1);
    repack_b<<<(1024 * 512 + 512 * 512) / 256, 256>>>(Wq, Wv, Wup, b1, b2);

    gemm_mma<<<dim3(1024 / 128, M_ROWS / 128), 128, SMEM_BYTES>>>(
        a1, b1, qv, 1024, 1.0f / BSCALE);
    band_attn_kernel<<<2 * NHEAD * (N_SEQ / TILE_I), 256>>>(qv, a2);
    gemm_mma<<<dim3(512 / 128, M_ROWS / 128), 128, SMEM_BYTES>>>(
        a2, b2, out, 512, 1.0f / (BSCALE * CSCALE));
}

// round 9
// speedup vs baseline: 2.7474x; 1.0877x over previous
#include <cuda_runtime.h>
#include <cuda_fp16.h>
#include <cstdint>

// ----------------------------------------------------------------------------
// MultiHeadAttn via fp16 2-term split + mma.sync:
//   A side exact: A' = [A_hi | A_lo] fp16 (K'=1024); B side hi-only, scaled 2^13.
//   1) convert_x : x[8192,512] -> A1 fp16 [8192,1024]  (hi|lo)
//   2) repack_b  : Wq,Wv -> B1 fp16 [1024,512] (x8192); Wup -> B2 [512,512] (x8192)
//   3) gemm_mma  : QV[8192,1024] fp32 = A1 @ B1dup^T, escale=2^-13
//   4) band_attn : half2 smem tiles; HFMA2 scores; fp32 phase C; QV -> A2 hi|lo
//   5) gemm_mma  : out[8192,512] = A2 @ B2dup^T, escale=2^-21
// ----------------------------------------------------------------------------

#define M_ROWS   8192
#define N_SEQ    4096
#define NHEAD    8
#define CONTEXT  10
#define KBIG     1024
#define NCHUNK   16          // 1024 / 64

#define BSCALE   8192.0f     // 2^13
#define CSCALE   256.0f      // 2^8
#define QSCALE   4096.0f     // 2^12: keeps fp16 score products in normal range

__device__ __half g_A1[M_ROWS * KBIG];
__device__ __half g_A2[M_ROWS * KBIG];
__device__ __half g_B1[1024 * 512];
__device__ __half g_B2[512  * 512];
__device__ float  g_QV[M_ROWS * 1024];

// ============================ PTX helpers ====================================
__device__ __forceinline__ uint32_t smem_u32(const void* p) {
    uint32_t a;
    asm("{ .reg .u64 t; cvta.to.shared.u64 t, %1; cvt.u32.u64 %0, t; }"
        : "=r"(a) : "l"(p));
    return a;
}
__device__ __forceinline__ void cp_async16(uint32_t dst, const void* src) {
    asm volatile("cp.async.cg.shared.global [%0], [%1], 16;"
                 :: "r"(dst), "l"(src) : "memory");
}
__device__ __forceinline__ void cp_commit() {
    asm volatile("cp.async.commit_group;" ::: "memory");
}
template <int N>
__device__ __forceinline__ void cp_wait() {
    asm volatile("cp.async.wait_group %0;" :: "n"(N) : "memory");
}
__device__ __forceinline__ void ldm_x4(uint32_t& r0, uint32_t& r1,
                                       uint32_t& r2, uint32_t& r3, uint32_t a) {
    asm volatile("ldmatrix.sync.aligned.m8n8.x4.shared.b16 {%0,%1,%2,%3}, [%4];"
                 : "=r"(r0), "=r"(r1), "=r"(r2), "=r"(r3) : "r"(a));
}
__device__ __forceinline__ void mma16816(float* c, const uint32_t* a,
                                         const uint32_t* b) {
    asm volatile(
        "mma.sync.aligned.m16n8k16.row.col.f32.f16.f16.f32 "
        "{%0,%1,%2,%3}, {%4,%5,%6,%7}, {%8,%9}, {%0,%1,%2,%3};"
        : "+f"(c[0]), "+f"(c[1]), "+f"(c[2]), "+f"(c[3])
        : "r"(a[0]), "r"(a[1]), "r"(a[2]), "r"(a[3]), "r"(b[0]), "r"(b[1]));
}
__device__ __forceinline__ __half2 u2h(uint32_t v) {
    return *reinterpret_cast<__half2*>(&v);
}

// ======================= conversion / repack kernels =========================
__global__ void convert_x(const float* __restrict__ x,
                          __half* __restrict__ A1) {
    int idx = blockIdx.x * 256 + threadIdx.x;       // [0, 8192*128)
    int row = idx >> 7;
    int kq  = (idx & 127) * 4;
    float4 v = *(const float4*)(x + (size_t)row * 512 + kq);
    __half h0 = __float2half_rn(v.x), h1 = __float2half_rn(v.y);
    __half h2 = __float2half_rn(v.z), h3 = __float2half_rn(v.w);
    __half l0 = __float2half_rn(v.x - __half2float(h0));
    __half l1 = __float2half_rn(v.y - __half2float(h1));
    __half l2 = __float2half_rn(v.z - __half2float(h2));
    __half l3 = __float2half_rn(v.w - __half2float(h3));
    __half* p = A1 + (size_t)row * KBIG;
    __half2 hv[2] = {__halves2half2(h0, h1), __halves2half2(h2, h3)};
    __half2 lv[2] = {__halves2half2(l0, l1), __halves2half2(l2, l3)};
    *(uint2*)&p[kq]       = *(uint2*)hv;
    *(uint2*)&p[512 + kq] = *(uint2*)lv;
}

__global__ void repack_b(const float* __restrict__ Wq,
                         const float* __restrict__ Wv,
                         const float* __restrict__ Wup,
                         __half* __restrict__ B1,
                         __half* __restrict__ B2) {
    int idx = blockIdx.x * 256 + threadIdx.x;       // [0, 1024*512 + 512*512)
    if (idx < 1024 * 512) {
        int n = idx >> 9, d = idx & 511;
        float w;
        if (n < 512) {
            int hh = n >> 6, k2 = n & 63;
            w = Wq[hh * (512 * 64) + d * 64 + k2];
        } else {
            int nn = n - 512, hh = nn >> 6, k2 = nn & 63;
            w = Wv[hh * (512 * 64) + d * 64 + k2];
        }
        B1[n * 512 + d] = __float2half_rn(w * BSCALE);
    } else {
        int i2 = idx - 1024 * 512;
        int n = i2 >> 9, d = i2 & 511;
        B2[n * 512 + d] = __float2half_rn(Wup[d * 512 + n] * BSCALE);
    }
}

// ====================== HMMA fp16 GEMM =======================================
__device__ __forceinline__ void load_tiles(uint32_t sA, uint32_t sB,
                                           const __half* __restrict__ A,
                                           const __half* __restrict__ B,
                                           int bm, int bn, int ck, int tid) {
    const __half* Ab = A + (size_t)bm * KBIG + ck * 64;
    const __half* Bb = B + (size_t)bn * 512 + (ck & 7) * 64;  // B dup: hi twice
    #pragma unroll
    for (int g = 0; g < 8; g++) {
        int id  = g * 128 + tid;         // 0..1023 granules of 16B
        int row = id >> 3;               // 0..127
        int c16 = id & 7;                // 0..7
        uint32_t sw = row * 128 + ((c16 * 16) ^ ((row & 7) * 16));
        cp_async16(sA + sw, Ab + (size_t)row * KBIG + c16 * 8);
        cp_async16(sB + sw, Bb + (size_t)row * 512 + c16 * 8);
    }
}

__global__ __launch_bounds__(128)
void gemm_mma(const __half* __restrict__ A,
              const __half* __restrict__ B,
              float* __restrict__ C, int N, float escale) {
    extern __shared__ char smem[];
    uint32_t sb = smem_u32(smem);
    uint32_t SA[3] = {sb, sb + 32768, sb + 65536};
    uint32_t SB[3] = {sb + 16384, sb + 49152, sb + 81920};

    const int tid  = threadIdx.x;
    const int lane = tid & 31;
    const int warp = tid >> 5;
    const int wm   = (warp >> 1) * 64;
    const int wn   = (warp & 1) * 64;
    const int bm   = blockIdx.y * 128, bn = blockIdx.x * 128;

    const int fr = (lane & 7) + ((lane >> 3) & 1) * 8;
    const int fk = (lane >> 4) * 16;

    float acc[4][8][4];
    #pragma unroll
    for (int i = 0; i < 4; i++)
        #pragma unroll
        for (int j = 0; j < 8; j++)
            #pragma unroll
            for (int q = 0; q < 4; q++) acc[i][j][q] = 0.f;

    load_tiles(SA[0], SB[0], A, B, bm, bn, 0, tid); cp_commit();
    load_tiles(SA[1], SB[1], A, B, bm, bn, 1, tid); cp_commit();

    #pragma unroll 1
    for (int c = 0; c < NCHUNK; c++) {
        const int s = c % 3;
        uint32_t sA = SA[s], sBt = SB[s];

        if (c == NCHUNK - 1) cp_wait<0>(); else cp_wait<1>();
        __syncthreads();

        if (c + 2 < NCHUNK) {
            const int s2 = (c + 2) % 3;
            load_tiles(SA[s2], SB[s2], A, B, bm, bn, c + 2, tid);
            cp_commit();
        }

        #pragma unroll
        for (int ks = 0; ks < 4; ks++) {
            const int k0b = ks * 32;
            uint32_t af[4][4], bf[8][2];
            #pragma unroll
            for (int mi = 0; mi < 4; mi++) {
                int r = wm + mi * 16 + fr;
                uint32_t addr = sA + r * 128 + ((k0b + fk) ^ ((r & 7) * 16));
                ldm_x4(af[mi][0], af[mi][1], af[mi][2], af[mi][3], addr);
            }
            #pragma unroll
            for (int ni = 0; ni < 4; ni++) {
                int r = wn + ni * 16 + fr;
                uint32_t addr = sBt + r * 128 + ((k0b + fk) ^ ((r & 7) * 16));
                uint32_t r0, r1, r2, r3;
                ldm_x4(r0, r1, r2, r3, addr);
                bf[2 * ni][0]     = r0; bf[2 * ni][1]     = r2;
                bf[2 * ni + 1][0] = r1; bf[2 * ni + 1][1] = r3;
            }
            #pragma unroll
            for (int mi = 0; mi < 4; mi++)
                #pragma unroll
                for (int nj = 0; nj < 8; nj++)
                    mma16816(acc[mi][nj], af[mi], bf[nj]);
        }
    }

    const int er = lane >> 2;
    const int ec = (lane & 3) * 2;
    #pragma unroll
    for (int mi = 0; mi < 4; mi++) {
        #pragma unroll
        for (int nj = 0; nj < 8; nj++) {
            int row = bm + wm + mi * 16 + er;
            int col = bn + wn + nj * 8 + ec;
            *(float2*)(C + (size_t)row * N + col) =
                make_float2(acc[mi][nj][0] * escale, acc[mi][nj][1] * escale);
            *(float2*)(C + (size_t)(row + 8) * N + col) =
                make_float2(acc[mi][nj][2] * escale, acc[mi][nj][3] * escale);
        }
    }
}

// ============================ band attention =================================
// half2 smem tiles, pitch 72 halves (144B: 16B-aligned rows, lane stride
// = 36 banks = 4 mod 32 -> conflict-free uint4 phase A and LDS.32 phase C).
// Q stored pre-scaled by 2^12 so fp16 score products stay in normal range.
#define TILE_I  64
#define VROWS   (TILE_I + 2 * CONTEXT)   // 84
#define PITCH_H 72

__global__ __launch_bounds__(256)
void band_attn_kernel(const float* __restrict__ QV,
                      __half* __restrict__ A2) {
    __shared__ __half Vs[VROWS * PITCH_H];   // 12096 B
    __shared__ __half Qs[TILE_I * PITCH_H];  //  9216 B

    const int bx   = blockIdx.x;
    const int tile = bx & 63;
    const int hd   = (bx >> 6) & 7;
    const int b    = bx >> 9;
    const int i0   = tile * TILE_I;
    const int tid  = threadIdx.x;
    const int lane = tid & 31;
    const int warp = tid >> 5;

    // load V band rows -> half2 (zero-fill out-of-range)
    for (int idx = tid; idx < VROWS * 16; idx += 256) {
        int r  = idx >> 4;
        int kq = idx & 15;
        int j  = i0 - CONTEXT + r;
        float4 v = make_float4(0.f, 0.f, 0.f, 0.f);
        if (j >= 0 && j < N_SEQ)
            v = *(const float4*)(QV + (b * N_SEQ + j) * 1024 + 512 + hd * 64 + kq * 4);
        __half2 p0 = __floats2half2_rn(v.x, v.y);
        __half2 p1 = __floats2half2_rn(v.z, v.w);
        uint2 pk = make_uint2(*(uint32_t*)&p0, *(uint32_t*)&p1);
        *(uint2*)&Vs[r * PITCH_H + kq * 4] = pk;
    }
    // load Q rows scaled by 2^12 -> half2
    for (int idx = tid; idx < TILE_I * 16; idx += 256) {
        int r  = idx >> 4;
        int kq = idx & 15;
        float4 v = *(const float4*)(QV + (b * N_SEQ + i0 + r) * 1024 + hd * 64 + kq * 4);
        __half2 p0 = __floats2half2_rn(v.x * QSCALE, v.y * QSCALE);
        __half2 p1 = __floats2half2_rn(v.z * QSCALE, v.w * QSCALE);
        uint2 pk = make_uint2(*(uint32_t*)&p0, *(uint32_t*)&p1);
        *(uint2*)&Qs[r * PITCH_H + kq * 4] = pk;
    }
    __syncthreads();

    for (int t = 0; t < 8; t++) {
        int il = warp * 8 + t;
        int i  = i0 + il;

        // phase A: lane L -> offset d = L-10; HFMA2 dot on half2 tiles
        float s = -1e30f;
        if (lane < 21 && lane != CONTEXT) {
            int j = i + lane - CONTEXT;
            if (j >= 0 && j < N_SEQ) {
                const uint4* qp = (const uint4*)&Qs[il * PITCH_H];
                const uint4* vp = (const uint4*)&Vs[(il + lane) * PITCH_H];
                __half2 acc2 = __float2half2_rn(0.f);
                #pragma unroll
                for (int k = 0; k < 8; k++) {
                    uint4 qa = qp[k], vb = vp[k];
                    acc2 = __hfma2(u2h(qa.x), u2h(vb.x), acc2);
                    acc2 = __hfma2(u2h(qa.y), u2h(vb.y), acc2);
                    acc2 = __hfma2(u2h(qa.z), u2h(vb.z), acc2);
                    acc2 = __hfma2(u2h(qa.w), u2h(vb.w), acc2);
                }
                float sacc = __low2float(acc2) + __high2float(acc2);
                s = sacc * (1.0f / (16.0f * QSCALE));
            }
        }

        // phase B: softmax across band lanes
        float mx = s;
        #pragma unroll
        for (int o = 16; o > 0; o >>= 1)
            mx = fmaxf(mx, __shfl_xor_sync(0xffffffffu, mx, o));
        float p = __expf(s - mx);
        float sum = p;
        #pragma unroll
        for (int o = 16; o > 0; o >>= 1)
            sum += __shfl_xor_sync(0xffffffffu, sum, o);
        float w = p / sum;

        // phase C: fp32 accumulate over half2 V reads; lane -> k = 2l, 2l+1
        float a0 = 0.f, a1 = 0.f;
        #pragma unroll
        for (int jj = 0; jj < 21; jj++) {
            float wj = __shfl_sync(0xffffffffu, w, jj);
            __half2 vv = *(const __half2*)&Vs[(il + jj) * PITCH_H + 2 * lane];
            float2 vf = __half22float2(vv);
            a0 += wj * vf.x;
            a1 += wj * vf.y;
        }
        // scaled split store: C*256 -> [hi | lo] half2
        float s0 = a0 * CSCALE, s1 = a1 * CSCALE;
        __half h0 = __float2half_rn(s0), h1 = __float2half_rn(s1);
        __half l0 = __float2half_rn(s0 - __half2float(h0));
        __half l1 = __float2half_rn(s1 - __half2float(h1));
        __half* cp = A2 + (size_t)(b * N_SEQ + i) * KBIG + hd * 64;
        *(__half2*)&cp[2 * lane]       = __halves2half2(h0, h1);
        *(__half2*)&cp[512 + 2 * lane] = __halves2half2(l0, l1);
    }
}

// ================================ launch =====================================
extern "C" void kernel_launch(void* const* d_in, const int* in_sizes, int n_in,
                              void* d_out, int out_size) {
    const float* x   = (const float*)d_in[0];
    const float* Wq  = (const float*)d_in[1];
    const float* Wv  = (const float*)d_in[2];
    const float* Wup = (const float*)d_in[3];
    float* out = (float*)d_out;

    __half *a1, *a2, *b1, *b2;
    float *qv;
    cudaGetSymbolAddress((void**)&a1, g_A1);
    cudaGetSymbolAddress((void**)&a2, g_A2);
    cudaGetSymbolAddress((void**)&b1, g_B1);
    cudaGetSymbolAddress((void**)&b2, g_B2);
    cudaGetSymbolAddress((void**)&qv, g_QV);

    const int SMEM_BYTES = 98304;   // 3 stages x 32KB
    cudaFuncSetAttribute(gemm_mma, cudaFuncAttributeMaxDynamicSharedMemorySize,
                         SMEM_BYTES);

    convert_x<<<(M_ROWS * 128) / 256, 256>>>(x, a1);
    repack_b<<<(1024 * 512 + 512 * 512) / 256, 256>>>(Wq, Wv, Wup, b1, b2);

    gemm_mma<<<dim3(1024 / 128, M_ROWS / 128), 128, SMEM_BYTES>>>(
        a1, b1, qv, 1024, 1.0f / BSCALE);
    band_attn_kernel<<<2 * NHEAD * (N_SEQ / TILE_I), 256>>>(qv, a2);
    gemm_mma<<<dim3(512 / 128, M_ROWS / 128), 128, SMEM_BYTES>>>(
        a2, b2, out, 512, 1.0f / (BSCALE * CSCALE));
}